// round 13
// baseline (speedup 1.0000x reference)
#include <cuda_runtime.h>
#include <cuda_bf16.h>
#include <cstdint>

#define T_STEPS 512
#define N_BATCH 64
#define C_IN    512
#define H_DIM   1024
#define P_DIM   512
#define G4H     4096
#define M_TOTAL (T_STEPS * N_BATCH)   /* 32768 */
#define NBLK    128
#define NTHR    512
#define CHUNK_SZ 33792                /* one hvec chunk buffer (64 rows x 528) */

// ---------------- scratch (device globals: no runtime allocation allowed) -------------
__device__ float g_pre[(size_t)G4H * M_TOTAL];            // pre^T [g][m], 512 MB
__device__ float g_wc[(size_t)G4H * H_DIM];               // Wcomb = Wr@Wo fp32, 16 MB
__device__ __nv_bfloat16 g_hall[(size_t)M_TOTAL * 2048];  // hvec archive [t*64+n][hi1024|lo1024]
__device__ unsigned g_count;                              // legacy barrier counter
__device__ unsigned g_sense;                              // legacy barrier sense
__device__ unsigned g_flags[NBLK * 64];                   // flag barrier: 1 flag / 256B line
__device__ __nv_bfloat16 g_xs[(size_t)M_TOTAL * 1536];    // x split   [m][hi|lo|hi]
__device__ __nv_bfloat16 g_ws[(size_t)G4H * 1536];        // wx split  [g][hi|hi|lo]
__device__ __nv_bfloat16 g_wrs[(size_t)G4H * 1536];       // wr split  [g][hi|hi|lo]
__device__ __nv_bfloat16 g_wts[(size_t)H_DIM * 1536];     // wo^T split[h][hi|lo|hi]
__device__ __nv_bfloat16 g_wos[(size_t)P_DIM * 3072];     // wo split  [p][hi|hi|lo] (K=1024)

// ---------------- small helpers --------------------------------------------------------
__device__ __forceinline__ void cpa16s(uint32_t smem_dst, const void* gsrc) {
    asm volatile("cp.async.cg.shared.global [%0], [%1], 16;" :: "r"(smem_dst), "l"(gsrc));
}
#define CP_COMMIT() asm volatile("cp.async.commit_group;" ::: "memory")
#define CP_WAIT0()  asm volatile("cp.async.wait_group 0;" ::: "memory")
#define CP_WAIT1()  asm volatile("cp.async.wait_group 1;" ::: "memory")
#define CP_WAIT2()  asm volatile("cp.async.wait_group 2;" ::: "memory")
__device__ __forceinline__ void wait_pending(int n) {
    if (n <= 0) { CP_WAIT0(); } else if (n == 1) { CP_WAIT1(); } else { CP_WAIT2(); }
}

__device__ __forceinline__ float sigmoidf_(float x) {
    return 1.0f / (1.0f + __expf(-x));
}
__device__ __forceinline__ float tanhf_(float x) {
    float e = __expf(-2.0f * fabsf(x));
    float t = (1.0f - e) / (1.0f + e);
    return copysignf(t, x);
}
__device__ __forceinline__ uint32_t smem_u32(const void* p) {
    return (uint32_t)__cvta_generic_to_shared(p);
}
__device__ __forceinline__ void stcg_u32(void* p, uint32_t v) {
    asm volatile("st.global.cg.u32 [%0], %1;" :: "l"(p), "r"(v) : "memory");
}
__device__ __forceinline__ unsigned short bf_bits(__nv_bfloat16 h) {
    unsigned short u; __builtin_memcpy(&u, &h, 2); return u;
}

// ---------------- HMMA helpers (sm_80+ baseline PTX: valid at compute_103) ------------
__device__ __forceinline__ void ldm_x4(uint32_t &r0, uint32_t &r1, uint32_t &r2,
                                       uint32_t &r3, uint32_t a) {
    asm volatile("ldmatrix.sync.aligned.m8n8.x4.shared.b16 {%0,%1,%2,%3}, [%4];"
                 : "=r"(r0), "=r"(r1), "=r"(r2), "=r"(r3) : "r"(a));
}
__device__ __forceinline__ void mma_bf16(float* d, const uint32_t* a, const uint32_t* b) {
    asm volatile("mma.sync.aligned.m16n8k16.row.col.f32.bf16.bf16.f32 "
                 "{%0,%1,%2,%3}, {%4,%5,%6,%7}, {%8,%9}, {%0,%1,%2,%3};"
                 : "+f"(d[0]), "+f"(d[1]), "+f"(d[2]), "+f"(d[3])
                 : "r"(a[0]), "r"(a[1]), "r"(a[2]), "r"(a[3]),
                   "r"(b[0]), "r"(b[1]));
}

// ---------------- legacy atomic grid barrier (2x per lstm_rec launch) -----------------
__device__ __forceinline__ void grid_barrier(unsigned &sense_local) {
    __syncthreads();
    if (threadIdx.x == 0) {
        unsigned s = sense_local ^ 1u;
        unsigned prev;
        asm volatile("atom.acq_rel.gpu.global.add.u32 %0, [%1], %2;"
                     : "=r"(prev) : "l"(&g_count), "r"(1u) : "memory");
        if (prev == gridDim.x - 1) {
            g_count = 0;
            asm volatile("st.release.gpu.global.u32 [%0], %1;"
                         :: "l"(&g_sense), "r"(s) : "memory");
        } else {
            unsigned v;
            do {
                asm volatile("ld.acquire.gpu.global.u32 %0, [%1];"
                             : "=r"(v) : "l"(&g_sense) : "memory");
            } while (v != s);
        }
    }
    __syncthreads();
    sense_local ^= 1u;
}

// ---------------- flag-array grid barrier (known good) --------------------------------
__device__ __forceinline__ void flag_barrier(unsigned s) {
    __syncthreads();
    if (threadIdx.x == 0)
        asm volatile("st.release.gpu.global.u32 [%0], %1;"
                     :: "l"(&g_flags[blockIdx.x * 64]), "r"(s) : "memory");
    if (threadIdx.x < NBLK) {
        const unsigned* p = &g_flags[threadIdx.x * 64];
        unsigned v;
        do {
            asm volatile("ld.acquire.gpu.global.u32 %0, [%1];"
                         : "=r"(v) : "l"(p) : "memory");
        } while ((int)(v - s) < 0);
    }
    __syncthreads();
}

// ---------------- split kernels --------------------------------------------------------
__global__ void splitk(const float* __restrict__ src, __nv_bfloat16* __restrict__ dst,
                       int total, int rl2, int mode) {
    const int rowmask = (1 << rl2) - 1;
    const int rowlen = 1 << rl2;
    for (int i = blockIdx.x * blockDim.x + threadIdx.x; i < total;
         i += gridDim.x * blockDim.x) {
        int row = i >> rl2, k = i & rowmask;
        float v = src[i];
        __nv_bfloat16 h = __float2bfloat16(v);
        __nv_bfloat16 l = __float2bfloat16(v - __bfloat162float(h));
        __nv_bfloat16* d = dst + (size_t)row * 3 * rowlen + k;
        d[0] = h;
        d[rowlen]     = mode ? h : l;
        d[2 * rowlen] = mode ? l : h;
    }
}
__global__ void splitt(const float* __restrict__ wo, __nv_bfloat16* __restrict__ dst) {
    for (int i = blockIdx.x * blockDim.x + threadIdx.x; i < P_DIM * H_DIM;
         i += gridDim.x * blockDim.x) {
        int p = i >> 10, h = i & 1023;
        float v = wo[i];
        __nv_bfloat16 hi = __float2bfloat16(v);
        __nv_bfloat16 lo = __float2bfloat16(v - __bfloat162float(hi));
        __nv_bfloat16* d = dst + (size_t)h * 1536 + p;
        d[0] = hi; d[512] = lo; d[1024] = hi;
    }
}

// ---------------- generic HMMA GEMM (proven mainloop, unchanged) -----------------------
#define PTHR 512
#define A_STG 20480
#define B_STG 10240
#define STG   (A_STG + B_STG)
#define GEN_SMEM (2 * STG + 256)

__global__ __launch_bounds__(PTHR, 1)
void hmma_gemm(const __nv_bfloat16* __restrict__ A, const __nv_bfloat16* __restrict__ B,
               int apitch, int bpitch, int ktot, int bwrapk, int mode,
               const float* __restrict__ bias, float* __restrict__ outp,
               const void* __restrict__ Lraw) {
    extern __shared__ char smc[];
    const uint32_t sb = smem_u32(smc);
    int* s_len = (int*)(smc + 2 * STG);
    const int tid = threadIdx.x, lane = tid & 31, warp = tid >> 5;
    const int wg = warp >> 2;
    const int wm = warp & 3;
    const int g0 = blockIdx.x * 256;
    const int m0 = blockIdx.y * 128;

    if (mode == 2 && tid < 64) {
        long long first = *(const long long*)Lraw;
        bool i64 = (first >= 1 && first <= (long long)T_STEPS);
        long long L = i64 ? ((const long long*)Lraw)[tid]
                          : (long long)((const int*)Lraw)[tid];
        s_len[tid] = (int)L;
    }

    float acc[4][4][4];
#pragma unroll
    for (int a = 0; a < 4; a++)
#pragma unroll
        for (int b = 0; b < 4; b++)
#pragma unroll
            for (int c = 0; c < 4; c++) acc[a][b][c] = 0.0f;

    const int a_r = lane & 15;
    const int a_k = (lane & 16) ? 8 : 0;
    const int b_r = (lane & 7) + ((lane & 16) ? 8 : 0);
    const int b_k = (lane & 8) ? 8 : 0;
    const int nk = ktot / 32;

#pragma unroll 1
    for (int c = 0; c < nk + 1; c++) {
        if (c < nk) {
            const int k0 = c * 32;
            const uint32_t ba = sb + (c & 1) * STG;
            const int kkb = (k0 >= bwrapk) ? k0 - bwrapk : k0;
#pragma unroll
            for (int s = 0; s < 3; s++) {
                int f = tid + s * PTHR;
                if (f < 1024) {
                    int row = f >> 2, seg = f & 3;
                    cpa16s(ba + row * 80 + seg * 16,
                           (const char*)A + (size_t)(g0 + row) * apitch + (size_t)k0 * 2 + seg * 16);
                } else {
                    int f2 = f - 1024;
                    int row = f2 >> 2, seg = f2 & 3;
                    cpa16s(ba + A_STG + row * 80 + seg * 16,
                           (const char*)B + (size_t)(m0 + row) * bpitch + (size_t)kkb * 2 + seg * 16);
                }
            }
            CP_COMMIT();
        }
        if (c == 0) continue;
        const int cc = c - 1;
        if (c < nk) CP_WAIT1(); else CP_WAIT0();
        __syncthreads();

        const uint32_t abase = sb + (cc & 1) * STG + (wg * 64 + a_r) * 80 + a_k * 2;
        const uint32_t bbase = sb + (cc & 1) * STG + A_STG + (wm * 32 + b_r) * 80 + b_k * 2;
#pragma unroll
        for (int kh = 0; kh < 2; kh++) {
            uint32_t af[4][4], bf[2][4];
#pragma unroll
            for (int gi = 0; gi < 4; gi++)
                ldm_x4(af[gi][0], af[gi][1], af[gi][2], af[gi][3],
                       abase + gi * 16 * 80 + kh * 32);
#pragma unroll
            for (int bj = 0; bj < 2; bj++)
                ldm_x4(bf[bj][0], bf[bj][1], bf[bj][2], bf[bj][3],
                       bbase + bj * 16 * 80 + kh * 32);
#pragma unroll
            for (int gi = 0; gi < 4; gi++)
#pragma unroll
                for (int mj = 0; mj < 4; mj++)
                    mma_bf16(acc[gi][mj], af[gi], &bf[mj >> 1][(mj & 1) * 2]);
        }
        __syncthreads();
    }

    if (mode == 0) {
#pragma unroll
        for (int gi = 0; gi < 4; gi++) {
            const int gr = g0 + wg * 64 + gi * 16 + (lane >> 2);
            const float blo = __ldg(bias + gr);
            const float bhi = __ldg(bias + gr + 8);
#pragma unroll
            for (int mj = 0; mj < 4; mj++) {
                const int mc = m0 + wm * 32 + mj * 8 + (lane & 3) * 2;
                float2 v0 = { acc[gi][mj][0] + blo, acc[gi][mj][1] + blo };
                float2 v1 = { acc[gi][mj][2] + bhi, acc[gi][mj][3] + bhi };
                *(float2*)(g_pre + (size_t)gr * M_TOTAL + mc) = v0;
                *(float2*)(g_pre + (size_t)(gr + 8) * M_TOTAL + mc) = v1;
            }
        }
    } else if (mode == 1) {
#pragma unroll
        for (int gi = 0; gi < 4; gi++) {
            const int gr = g0 + wg * 64 + gi * 16 + (lane >> 2);
#pragma unroll
            for (int mj = 0; mj < 4; mj++) {
                const int mc = m0 + wm * 32 + mj * 8 + (lane & 3) * 2;
                float2 v0 = { acc[gi][mj][0], acc[gi][mj][1] };
                float2 v1 = { acc[gi][mj][2], acc[gi][mj][3] };
                *(float2*)(g_wc + (size_t)gr * H_DIM + mc) = v0;
                *(float2*)(g_wc + (size_t)(gr + 8) * H_DIM + mc) = v1;
            }
        }
    } else {
#pragma unroll
        for (int gi = 0; gi < 4; gi++) {
            const int gr = g0 + wg * 64 + gi * 16 + (lane >> 2);
#pragma unroll
            for (int mj = 0; mj < 4; mj++) {
                const int mc = m0 + wm * 32 + mj * 8 + (lane & 3) * 2;
                int t0 = mc >> 6, n0 = mc & 63;
                int t1 = (mc + 1) >> 6, n1 = (mc + 1) & 63;
                bool k0v = (t0 < s_len[n0]), k1v = (t1 < s_len[n1]);
                outp[(size_t)mc * P_DIM + gr]           = k0v ? acc[gi][mj][0] : 0.0f;
                outp[(size_t)(mc + 1) * P_DIM + gr]     = k1v ? acc[gi][mj][1] : 0.0f;
                outp[(size_t)mc * P_DIM + gr + 8]       = k0v ? acc[gi][mj][2] : 0.0f;
                outp[(size_t)(mc + 1) * P_DIM + gr + 8] = k1v ? acc[gi][mj][3] : 0.0f;
            }
        }
    }
}

// ---------------- Kernel: persistent LSTM recurrence (fused Wcomb, nbuf pipeline) -----
// g(t) = pre(t) + hvec(t-1) @ Wcomb^T ; gates; hvec(t) -> g_hall. 1 barrier/step.
// smem: CHUNKS @0: nbuf x 33792 (64 n rows x [hi 256B | lo 256B], pitch 528)
//       WCHI @nbuf*33792, WCLO @+65536: [gcol 32][2048 B], XOR-swizzled (seg ^= row&7)
__global__ __launch_bounds__(NTHR, 1)
void lstm_rec(const float* __restrict__ WCp, int nbuf, int wbase) {
    extern __shared__ char sm[];
    const uint32_t sb = smem_u32(sm);
    float* part = (float*)sm;

    const int tid = threadIdx.x;
    const int blk = blockIdx.x;
    const int lane = tid & 31, warp = tid >> 5;

    // ---- split Wcomb rows into smem bf16 hi/lo, XOR-swizzled layout ----
    // IDENTITY gcol row mapping (R10's permuted mapping was the 11.6% bug).
    {
        char* wch = sm + wbase;
        char* wcl = sm + wbase + 65536;
        for (int idx = tid; idx < 32 * 1024; idx += NTHR) {
            int gcol = idx >> 10, k = idx & 1023;
            int gate = gcol >> 3, hl = gcol & 7;
            float v = g_wc[(size_t)(gate * H_DIM + blk * 8 + hl) * H_DIM + k];
            __nv_bfloat16 h = __float2bfloat16(v);
            int off = gcol * 2048 + (((k >> 3) ^ (gcol & 7)) << 4) + (k & 7) * 2;
            *(__nv_bfloat16*)(wch + off) = h;
            *(__nv_bfloat16*)(wcl + off) = __float2bfloat16(v - __bfloat162float(h));
        }
    }

    // ---- roles (formulas preserved from R9/R11) ----
    const int mh  = warp & 1;
    const int ng  = (warp >> 1) & 1;
    const int kq1 = warp >> 2;
    const int n2 = (warp >> 2) * 32 + lane;
    const int hp = warp & 3;
    const int h0 = blk * 8 + hp * 2;

    const int a_r  = lane & 15;
    const int a_kb = (lane & 16) ? 16 : 0;
    const int b_r  = (lane & 7) + ((lane & 16) ? 8 : 0);
    const int b_kb = (lane & 8) ? 16 : 0;

    const float wci0 = WCp[h0],             wci1 = WCp[h0 + 1];
    const float wcf0 = WCp[H_DIM + h0],     wcf1 = WCp[H_DIM + h0 + 1];
    const float wco0 = WCp[2 * H_DIM + h0], wco1 = WCp[2 * H_DIM + h0 + 1];

    float c0 = 0.0f, c1 = 0.0f;
    unsigned sense = 0;
    float pv[8];

    if (tid == 0) g_flags[blk * 64] = 0u;
    grid_barrier(sense);

    // pre loads for step t (hoisted; overlaps barrier wait at step end)
    auto load_pre = [&](int tt) {
        if (warp < 8) {
            const int m = tt * N_BATCH + n2;
#pragma unroll
            for (int g = 0; g < 4; g++)
#pragma unroll
                for (int j = 0; j < 2; j++)
                    pv[g * 2 + j] =
                        __ldg(g_pre + (size_t)(g * H_DIM + h0 + j) * M_TOTAL + m);
        }
    };
    load_pre(0);

#pragma unroll 1
    for (int t = 0; t < T_STEPS; t++) {
        const char* hsrc = (const char*)g_hall + (size_t)(t - 1) * 64 * 4096;

        auto stage = [&](int cc, uint32_t db) {
            for (int g = tid; g < 2048; g += NTHR) {
                int row = g >> 5, gi = g & 31;
                if (gi < 16)
                    cpa16s(db + row * 528 + gi * 16,
                           hsrc + (size_t)row * 4096 + cc * 256 + gi * 16);
                else
                    cpa16s(db + row * 528 + 256 + (gi - 16) * 16,
                           hsrc + (size_t)row * 4096 + 2048 + cc * 256 + (gi - 16) * 16);
            }
            CP_COMMIT();
        };

        // prologue: stage first nbuf chunks of hvec(t-1)
        if (t > 0) {
            for (int ci = 0; ci < nbuf; ci++) stage(ci, sb + ci * CHUNK_SZ);
        }

        // fused GEMM: partial[n][gcol] = hvec(t-1) . Wcomb  (3-term, 8 chunks)
        if (t > 0) {
            float acc[2][2][4];
#pragma unroll
            for (int a = 0; a < 2; a++)
#pragma unroll
                for (int b = 0; b < 2; b++)
#pragma unroll
                    for (int c = 0; c < 4; c++) acc[a][b][c] = 0.0f;

            int bidx = 0;
#pragma unroll 1
            for (int c = 0; c < 8; c++) {
                int pend = 7 - c; if (pend > nbuf - 1) pend = nbuf - 1;
                wait_pending(pend);
                __syncthreads();
                const uint32_t hb = sb + bidx * CHUNK_SZ;
#pragma unroll
                for (int j = 0; j < 2; j++) {
                    const int k16l = kq1 * 2 + j;
                    const int kb  = k16l * 32;
                    const int kbw = (c * 8 + k16l) * 32;
                    uint32_t bh[4], bl[4];
                    const uint32_t brow = (uint32_t)(ng * 16 + b_r);
                    const uint32_t kseg = (uint32_t)(kbw + b_kb) >> 4;
                    const uint32_t wadr = sb + (uint32_t)wbase + brow * 2048 +
                                          ((kseg ^ (brow & 7u)) << 4);
                    ldm_x4(bh[0], bh[1], bh[2], bh[3], wadr);
                    ldm_x4(bl[0], bl[1], bl[2], bl[3], wadr + 65536);
#pragma unroll
                    for (int mi = 0; mi < 2; mi++) {
                        const uint32_t arow = (uint32_t)(mh * 32 + mi * 16 + a_r);
                        uint32_t ah[4], al[4];
                        ldm_x4(ah[0], ah[1], ah[2], ah[3],
                               hb + arow * 528 + kb + a_kb);
                        ldm_x4(al[0], al[1], al[2], al[3],
                               hb + arow * 528 + 256 + kb + a_kb);
#pragma unroll
                        for (int nj = 0; nj < 2; nj++) {
                            mma_bf16(acc[mi][nj], ah, &bh[nj * 2]);
                            mma_bf16(acc[mi][nj], al, &bh[nj * 2]);
                            mma_bf16(acc[mi][nj], ah, &bl[nj * 2]);
                        }
                    }
                }
                __syncthreads();
                if (c + nbuf < 8) stage(c + nbuf, sb + bidx * CHUNK_SZ);
                if (++bidx == nbuf) bidx = 0;
            }

            // partials: [kq][n][38] fp32 (overlay chunk buffers; reads all done)
#pragma unroll
            for (int mi = 0; mi < 2; mi++)
#pragma unroll
                for (int nj = 0; nj < 2; nj++) {
                    const int n  = mh * 32 + mi * 16 + (lane >> 2);
                    const int gc = ng * 16 + nj * 8 + (lane & 3) * 2;
                    float2 v0 = { acc[mi][nj][0], acc[mi][nj][1] };
                    float2 v1 = { acc[mi][nj][2], acc[mi][nj][3] };
                    *(float2*)&part[(kq1 * 64 + n) * 38 + gc] = v0;
                    *(float2*)&part[(kq1 * 64 + n + 8) * 38 + gc] = v1;
                }
            __syncthreads();
        }

        // gates (warps 0-7); hvec (hi+lo) -> g_hall[t]
        if (warp < 8) {
            float gv[8];
#pragma unroll
            for (int q = 0; q < 8; q++) gv[q] = pv[q];
            if (t > 0) {
#pragma unroll
                for (int gate = 0; gate < 4; gate++) {
                    const int gc = gate * 8 + hp * 2;
#pragma unroll
                    for (int kq = 0; kq < 4; kq++) {
                        float2 v = *(const float2*)&part[(kq * 64 + n2) * 38 + gc];
                        gv[gate * 2]     += v.x;
                        gv[gate * 2 + 1] += v.y;
                    }
                }
            }
            float in0 = sigmoidf_(gv[0] + wci0 * c0);
            float fg0 = sigmoidf_(gv[2] + wcf0 * c0);
            float cc0 = fg0 * c0 + in0 * tanhf_(gv[6]);
            float og0 = sigmoidf_(gv[4] + wco0 * cc0);
            float hv0 = og0 * tanhf_(cc0);
            c0 = cc0;
            float in1 = sigmoidf_(gv[1] + wci1 * c1);
            float fg1 = sigmoidf_(gv[3] + wcf1 * c1);
            float cc1 = fg1 * c1 + in1 * tanhf_(gv[7]);
            float og1 = sigmoidf_(gv[5] + wco1 * cc1);
            float hv1 = og1 * tanhf_(cc1);
            c1 = cc1;

            __nv_bfloat16 h0b = __float2bfloat16(hv0);
            __nv_bfloat16 h1b = __float2bfloat16(hv1);
            __nv_bfloat16 l0b = __float2bfloat16(hv0 - __bfloat162float(h0b));
            __nv_bfloat16 l1b = __float2bfloat16(hv1 - __bfloat162float(h1b));
            uint32_t hi2 = (uint32_t)bf_bits(h0b) | ((uint32_t)bf_bits(h1b) << 16);
            uint32_t lo2 = (uint32_t)bf_bits(l0b) | ((uint32_t)bf_bits(l1b) << 16);
            stcg_u32(g_hall + (size_t)(t * 64 + n2) * 2048 + h0, hi2);
            stcg_u32(g_hall + (size_t)(t * 64 + n2) * 2048 + 1024 + h0, lo2);
        }

        if (t + 1 < T_STEPS) load_pre(t + 1);   // overlap DRAM latency with barrier

        flag_barrier((unsigned)(t + 1));   // hvec(t) complete chip-wide
    }

    grid_barrier(sense);   // g_sense returns to launch-entry value (replay-safe)
}

// ---------------- launch ----------------------------------------------------------------
extern "C" void kernel_launch(void* const* d_in, const int* in_sizes, int n_in,
                              void* d_out, int out_size) {
    const float* x = nullptr;
    const void*  lengths = nullptr;
    const float* wx_w = nullptr;
    const float* wx_b = nullptr;
    const float* wr_w = nullptr;
    const float* wo_w = nullptr;
    const float* wc = nullptr;

    for (int i = 0; i < n_in; i++) {
        int s = in_sizes[i];
        if      (s == T_STEPS * N_BATCH * C_IN) x = (const float*)d_in[i];
        else if (s == N_BATCH)                  lengths = d_in[i];
        else if (s == 4 * H_DIM * C_IN) {
            if (!wx_w) wx_w = (const float*)d_in[i];
            else       wr_w = (const float*)d_in[i];
        }
        else if (s == 4 * H_DIM)                wx_b = (const float*)d_in[i];
        else if (s == P_DIM * H_DIM)            wo_w = (const float*)d_in[i];
        else if (s == 3 * H_DIM)                wc = (const float*)d_in[i];
    }

    __nv_bfloat16 *xs, *ws, *wrs, *wts, *wos, *hall;
    cudaGetSymbolAddress((void**)&xs,  g_xs);
    cudaGetSymbolAddress((void**)&ws,  g_ws);
    cudaGetSymbolAddress((void**)&wrs, g_wrs);
    cudaGetSymbolAddress((void**)&wts, g_wts);
    cudaGetSymbolAddress((void**)&wos, g_wos);
    cudaGetSymbolAddress((void**)&hall, g_hall);

    // splits
    splitk<<<4096, 256>>>(x,    xs,  M_TOTAL * C_IN, 9, 0);
    splitk<<<1024, 256>>>(wx_w, ws,  G4H * C_IN,     9, 1);
    splitk<<<512,  256>>>(wr_w, wrs, G4H * P_DIM,    9, 1);
    splitt<<<512,  256>>>(wo_w, wts);
    splitk<<<512,  256>>>(wo_w, wos, P_DIM * H_DIM, 10, 1);

    cudaFuncSetAttribute(hmma_gemm, cudaFuncAttributeMaxDynamicSharedMemorySize, GEN_SMEM);

    // pre-GEMM: pre^T[g][m]
    {
        dim3 g(G4H / 256, M_TOTAL / 128);
        hmma_gemm<<<g, PTHR, GEN_SMEM>>>(ws, xs, 3072, 3072, 1536, 1 << 30, 0,
                                         wx_b, nullptr, nullptr);
    }
    // Wcomb = Wr @ Wo  (fp32 out)
    {
        dim3 g(G4H / 256, H_DIM / 128);
        hmma_gemm<<<g, PTHR, GEN_SMEM>>>(wrs, wts, 3072, 3072, 1536, 1 << 30, 1,
                                         nullptr, nullptr, nullptr);
    }
    // recurrence: 3-deep pipeline if 227KB opt-in succeeds, else fall back to 2-deep
    int nbuf = 3;
    int rc_smem = 3 * CHUNK_SZ + 131072;   // 232448 = 227 KB
    if (cudaFuncSetAttribute(lstm_rec, cudaFuncAttributeMaxDynamicSharedMemorySize,
                             rc_smem) != cudaSuccess) {
        cudaGetLastError();                 // clear sticky error
        nbuf = 2;
        rc_smem = 2 * CHUNK_SZ + 131072;    // 198656
        cudaFuncSetAttribute(lstm_rec, cudaFuncAttributeMaxDynamicSharedMemorySize,
                             rc_smem);
    }
    lstm_rec<<<NBLK, NTHR, rc_smem>>>(wc, nbuf, nbuf * CHUNK_SZ);
    // final output: out[m][p] = Hall[m] . Wo[p], masked by lengths
    {
        dim3 g(P_DIM / 256, M_TOTAL / 128);
        hmma_gemm<<<g, PTHR, GEN_SMEM>>>(wos, hall, 6144, 4096, 3072, 2048, 2,
                                         nullptr, (float*)d_out, lengths);
    }
}